// round 10
// baseline (speedup 1.0000x reference)
#include <cuda_runtime.h>
#include <cstdint>

#define BB 4
#define FF 3
#define NPTS 8192
#define DD 16
#define KNN_K 32
#define OO 64
#define ALPHA 0.2f

#define GS 64                       // 64x64 grid over (x,y)
#define XG (-4.0f)
#define CW 0.125f                   // 2^-3, exact binary
#define INV_CW 8.0f
#define PRUNE_MARGIN 1e-3f
#define MIN_SEED 48

#define KNN_WARPS 8
#define PRE_BLOCKS 128              // 128*256 = 32768 = B*N

// Scratch (device globals -- no allocations allowed)
__device__ float  g_y1[BB * NPTS * OO];
__device__ float  g_c [BB * NPTS * OO];
__device__ int    g_idx[BB * NPTS * KNN_K];
__device__ float4 g_spts[BB * NPTS];             // cell-sorted (x,y,z, idx-bits)
__device__ int    g_cstart[BB * (GS * GS + 1)];  // cell CSR offsets

// ---------------------------------------------------------------------------
__device__ __forceinline__ int clampi(int v, int lo, int hi)
{ return min(max(v, lo), hi); }

__device__ __forceinline__ int cell_of(float px, float py)
{
    int ix = clampi((int)floorf((px - XG) * INV_CW), 0, GS - 1);
    int iy = clampi((int)floorf((py - XG) * INV_CW), 0, GS - 1);
    return iy * GS + ix;
}

// order-preserving float->u32 map and inverse
__device__ __forceinline__ unsigned mapf(float dpos)
{
    unsigned ub = __float_as_uint(dpos);
    return ub ^ (((unsigned)((int)ub >> 31)) | 0x80000000u);
}
__device__ __forceinline__ float unmapf(unsigned m)
{
    unsigned ub = (m & 0x80000000u) ? (m ^ 0x80000000u) : ~m;
    return __uint_as_float(ub);
}

// ---------------------------------------------------------------------------
// Kernel A: per-batch counting sort of points into 4096 (y,x) cells.
// ---------------------------------------------------------------------------
__global__ __launch_bounds__(1024) void sort_kernel(const float* __restrict__ points)
{
    __shared__ int hist[GS * GS];       // 16 KB
    __shared__ int wsum[32];
    const unsigned FULL = 0xFFFFFFFFu;
    int b = blockIdx.x, tid = threadIdx.x;
    const float* pb = points + b * FF * NPTS;

#pragma unroll
    for (int k = 0; k < 4; k++) hist[tid + k * 1024] = 0;
    __syncthreads();

    for (int m = tid; m < NPTS; m += 1024)
        atomicAdd(&hist[cell_of(pb[m], pb[NPTS + m])], 1);
    __syncthreads();

    // block exclusive scan over 4096 bins (4 bins/thread)
    int base = tid * 4;
    int c0 = hist[base], c1 = hist[base + 1], c2 = hist[base + 2], c3 = hist[base + 3];
    int tsum = c0 + c1 + c2 + c3;
    int lane = tid & 31, wid = tid >> 5;
    int v = tsum;
#pragma unroll
    for (int off = 1; off < 32; off <<= 1) {
        int u = __shfl_up_sync(FULL, v, off);
        if (lane >= off) v += u;
    }
    if (lane == 31) wsum[wid] = v;
    __syncthreads();
    if (tid < 32) {
        int w = wsum[tid];
#pragma unroll
        for (int off = 1; off < 32; off <<= 1) {
            int u = __shfl_up_sync(FULL, w, off);
            if (tid >= off) w += u;
        }
        wsum[tid] = w;                  // inclusive warp totals
    }
    __syncthreads();
    int ex = (v - tsum) + (wid > 0 ? wsum[wid - 1] : 0);
    int b0 = ex, b1 = ex + c0, b2 = b1 + c1, b3 = b2 + c2;
    int* cst = g_cstart + b * (GS * GS + 1);
    cst[base] = b0; cst[base + 1] = b1; cst[base + 2] = b2; cst[base + 3] = b3;
    if (tid == 0) cst[GS * GS] = NPTS;
    __syncthreads();
    hist[base] = b0; hist[base + 1] = b1; hist[base + 2] = b2; hist[base + 3] = b3;
    __syncthreads();

    for (int m = tid; m < NPTS; m += 1024) {
        float px = pb[m], py = pb[NPTS + m], pz = pb[2 * NPTS + m];
        int pos = atomicAdd(&hist[cell_of(px, py)], 1);
        g_spts[b * NPTS + pos] = make_float4(px, py, pz, __int_as_float(m));
    }
}

// ---------------------------------------------------------------------------
// Kernel B (fused): blocks [0,PRE_BLOCKS) = feature projections;
// rest = 2D-grid-pruned 32-NN, warp-per-query, batched-merge top-32.
//
// R10 change: the seed is a 2D expanding square around the query cell
// (count via CSR until >= MIN_SEED), so EVERY query (incl. sparse-edge)
// gets a tight real worst before the row walk. Rows inside the square
// stream only their side remainders; rows beyond stream their full
// conservative interval. No cell is processed twice (required: duplicate
// keys would corrupt the 32-list). Prune bounds, arithmetic, keys and
// merge identical to the validated R9 => identical neighbor sets.
// ---------------------------------------------------------------------------
__global__ __launch_bounds__(256) void fused_pre_knn_kernel(
    const float* __restrict__ points,
    const float* __restrict__ x,
    const float* __restrict__ W)
{
    __shared__ float sW[OO * 2 * DD];                    // precompute branch
    __shared__ int   scs[GS * GS + 1];                   // knn branch: cell CSR
    __shared__ unsigned long long sbuf[KNN_WARPS * 32];  // per-warp key buffer

    int tid = threadIdx.x;

    if (blockIdx.x < PRE_BLOCKS) {
        for (int i = tid; i < OO * 2 * DD; i += 256) sW[i] = W[i];
        __syncthreads();

        int gid = blockIdx.x * 256 + tid;
        int b = gid / NPTS, n = gid % NPTS;

        float xv[DD];
#pragma unroll
        for (int d = 0; d < DD; d++) xv[d] = x[(b * DD + d) * NPTS + n];

        float* y1p = &g_y1[(b * NPTS + n) * OO];
        float* cp  = &g_c [(b * NPTS + n) * OO];
#pragma unroll 4
        for (int o = 0; o < OO; o++) {
            float s1 = 0.f, s2 = 0.f;
#pragma unroll
            for (int d = 0; d < DD; d++) {
                s1 = __fmaf_rn(sW[o * 2 * DD + d],      xv[d], s1);
                s2 = __fmaf_rn(sW[o * 2 * DD + DD + d], xv[d], s2);
            }
            y1p[o] = s1;
            cp[o]  = s2 - s1;
        }
        return;
    }

    // ---------------------- knn: warp-per-query --------------------------
    int bid  = blockIdx.x - PRE_BLOCKS;
    int b    = bid >> 10;                        // 1024 blocks per batch
    int nblk = bid & 1023;
    int wid  = tid >> 5;
    int lane = tid & 31;
    int n = nblk * KNN_WARPS + wid;

    for (int j = tid; j < GS * GS + 1; j += 256)
        scs[j] = g_cstart[b * (GS * GS + 1) + j];
    __syncthreads();

    const float*  pb = points + b * FF * NPTS;
    const float4* sp = g_spts + b * NPTS;
    const unsigned FULL = 0xFFFFFFFFu;
    unsigned long long* wbuf = &sbuf[wid * 32];

    float qx = pb[n], qy = pb[NPTS + n], qz = pb[2 * NPTS + n];
    float xxn = __fadd_rn(__fadd_rn(__fmul_rn(qx, qx), __fmul_rn(qy, qy)),
                          __fmul_rn(qz, qz));
    float nxxn = -xxn;
    int qix = clampi((int)floorf((qx - XG) * INV_CW), 0, GS - 1);
    int qiy = clampi((int)floorf((qy - XG) * INV_CW), 0, GS - 1);

    unsigned long long listk = 0xFFFFFFFF00000000ULL | (unsigned)lane;
    unsigned long long worst = 0xFFFFFFFF0000001FULL;
    int nbuf = 0;                                // warp-uniform

    // flush: bitonic-sort buffer, half-clean vs list, bitonic re-merge
    auto flush = [&]() {
        __syncwarp(FULL);
        unsigned long long v = (lane < nbuf) ? wbuf[lane]
                                             : 0xFFFFFFFFFFFFFFFFULL;
#pragma unroll
        for (int k = 2; k <= 32; k <<= 1) {
#pragma unroll
            for (int j = k >> 1; j > 0; j >>= 1) {
                unsigned long long v2 = __shfl_xor_sync(FULL, v, j);
                bool asc   = ((lane & k) == 0);
                bool lower = ((lane & j) == 0);
                unsigned long long mn = (v < v2) ? v : v2;
                unsigned long long mx = (v < v2) ? v2 : v;
                v = (asc == lower) ? mn : mx;
            }
        }
        unsigned long long vr = __shfl_sync(FULL, v, 31 - lane);
        unsigned long long w = (listk < vr) ? listk : vr;
#pragma unroll
        for (int j = 16; j > 0; j >>= 1) {
            unsigned long long w2 = __shfl_xor_sync(FULL, w, j);
            bool lower = ((lane & j) == 0);
            unsigned long long mn = (w < w2) ? w : w2;
            unsigned long long mx = (w < w2) ? w2 : w;
            w = lower ? mn : mx;
        }
        listk = w;
        worst = __shfl_sync(FULL, listk, 31);
        nbuf = 0;
    };

    auto stream = [&](int beg, int end) {
        if (beg >= end) return;
        float4 c = (beg + lane < end) ? __ldg(&sp[beg + lane])
                                      : make_float4(0.f, 0.f, 0.f, 0.f);
        for (int g = beg; g < end; g += 32) {
            int i2 = g + 32 + lane;
            float4 cn = (i2 < end) ? __ldg(&sp[i2])
                                   : make_float4(0.f, 0.f, 0.f, 0.f);
            bool valid = (g + lane) < end;
            float xxm = __fadd_rn(
                __fadd_rn(__fmul_rn(c.x, c.x), __fmul_rn(c.y, c.y)),
                __fmul_rn(c.z, c.z));
            float ss = __fmul_rn(qx, c.x);
            ss = __fmaf_rn(qy, c.y, ss);
            ss = __fmaf_rn(qz, c.z, ss);
            float d = __fsub_rn(xxm, __fmaf_rn(ss, 2.0f, nxxn));
            unsigned long long key = valid
                ? (((unsigned long long)mapf(d) << 32) |
                   (unsigned)__float_as_int(c.w))
                : 0xFFFFFFFFFFFFFFFFULL;

            unsigned pass = __ballot_sync(FULL, key < worst);
            if (pass) {
                int npass = __popc(pass);
                if (nbuf + npass > 32) flush();          // warp-uniform
                int rank = __popc(pass & ((1u << lane) - 1u));
                if (pass & (1u << lane)) wbuf[nbuf + rank] = key;
                nbuf += npass;
            }
            c = cn;
        }
    };

    // conservative x-interval for a row; (1,0) only when row excluded
    auto rowrange = [&](int iy) -> int2 {
        float wd = unmapf((unsigned)(worst >> 32));
        if (wd != wd) return make_int2(0, GS - 1);     // sentinel: full row
        float dy = 0.f;
        if (iy > qiy)      dy = fmaxf(__fsub_rn(XG + (float)iy * CW, qy), 0.f);
        else if (iy < qiy) dy = fmaxf(__fsub_rn(qy, XG + (float)(iy + 1) * CW), 0.f);
        float rem = wd + PRUNE_MARGIN - __fmul_rn(dy, dy);
        if (rem < 0.f) return make_int2(1, 0);          // row excluded
        float rad = sqrtf(rem);
        int jlo = (int)floorf((qx - rad - XG) * INV_CW) - 1;
        int jhi = (int)floorf((qx + rad - XG) * INV_CW) + 1;
        jlo = clampi(jlo, 0, GS - 1);
        jhi = clampi(jhi, 0, GS - 1);
        return make_int2(jlo, jhi);
    };

    // ---- seed: expanding square around query cell until >= MIN_SEED ----
    int s = 0;
    int ry0 = qiy, ry1 = qiy, cx0 = qix, cx1 = qix;
    {
        int cnt = scs[qiy * GS + qix + 1] - scs[qiy * GS + qix];
        while (cnt < MIN_SEED && s < GS) {
            s++;
            ry0 = clampi(qiy - s, 0, GS - 1);
            ry1 = clampi(qiy + s, 0, GS - 1);
            cx0 = clampi(qix - s, 0, GS - 1);
            cx1 = clampi(qix + s, 0, GS - 1);
            cnt = 0;
            for (int iy = ry0; iy <= ry1; iy++)
                cnt += scs[iy * GS + cx1 + 1] - scs[iy * GS + cx0];
            if (ry0 == 0 && ry1 == GS - 1 && cx0 == 0 && cx1 == GS - 1) break;
        }
        for (int iy = ry0; iy <= ry1; iy++) {
            const int* rc = &scs[iy * GS];
            stream(rc[cx0], rc[cx1 + 1]);
        }
        if (nbuf > 0) flush();          // real worst for pruning
    }

    // ---- square rows: side remainders only (disjoint from square) ----
    for (int iy = ry0; iy <= ry1; iy++) {
        int2 rr = rowrange(iy);
        if (rr.x > rr.y) continue;
        const int* rc = &scs[iy * GS];
        if (rr.x < cx0) stream(rc[rr.x], rc[cx0]);
        if (rr.y > cx1) stream(rc[cx1 + 1], rc[rr.y + 1]);
    }

    // ---- walk remaining rows outward; stop a side when excluded ----
    int up = ry1 + 1, dn = ry0 - 1;
    bool goU = (up < GS), goD = (dn >= 0);
    while (goU || goD) {
        if (goU) {
            int2 rr = rowrange(up);
            if (rr.x > rr.y) goU = false;
            else {
                const int* rc = &scs[up * GS];
                stream(rc[rr.x], rc[rr.y + 1]);
                up++; if (up >= GS) goU = false;
            }
        }
        if (goD) {
            int2 rr = rowrange(dn);
            if (rr.x > rr.y) goD = false;
            else {
                const int* rc = &scs[dn * GS];
                stream(rc[rr.x], rc[rr.y + 1]);
                dn--; if (dn < 0) goD = false;
            }
        }
    }
    if (nbuf > 0) flush();

    g_idx[(b * NPTS + n) * KNN_K + lane] = (int)(listk & 0xFFFFFFFFu);
}

// ---------------------------------------------------------------------------
// Kernel 3: out[b][o][n] = (1/K) * sum_k leaky( y1[b][idx[n][k]][o] + c[b][n][o] )
// ---------------------------------------------------------------------------
__global__ __launch_bounds__(256) void edgeconv_kernel(float* __restrict__ out)
{
    __shared__ float stile[OO][33];
    __shared__ int   sidx[32 * KNN_K];

    int b = blockIdx.y;
    int nbase = blockIdx.x * 32;
    int tid = threadIdx.x;

    for (int i = tid; i < 32 * KNN_K; i += 256)
        sidx[i] = g_idx[(b * NPTS + nbase) * KNN_K + i];
    __syncthreads();

    int o = tid & 63;
    int sub = tid >> 6;

    for (int nt = 0; nt < 8; nt++) {
        int nl = nt * 4 + sub;
        int n = nbase + nl;
        float c = g_c[(b * NPTS + n) * OO + o];
        float acc = 0.f;
        const int* ip = &sidx[nl * KNN_K];
#pragma unroll 8
        for (int k = 0; k < KNN_K; k++) {
            int m = ip[k];
            float t = g_y1[(b * NPTS + m) * OO + o] + c;
            acc += (t >= 0.f) ? t : ALPHA * t;
        }
        stile[o][nl] = acc * (1.0f / KNN_K);
    }
    __syncthreads();

#pragma unroll
    for (int r = 0; r < 8; r++) {
        int oo = r * 8 + (tid >> 5);
        int nn = tid & 31;
        out[(b * OO + oo) * NPTS + nbase + nn] = stile[oo][nn];
    }
}

// ---------------------------------------------------------------------------
extern "C" void kernel_launch(void* const* d_in, const int* in_sizes, int n_in,
                              void* d_out, int out_size)
{
    const float* points = nullptr;
    const float* x = nullptr;
    const float* W = nullptr;
    for (int i = 0; i < n_in; i++) {
        if      (in_sizes[i] == BB * FF * NPTS) points = (const float*)d_in[i];
        else if (in_sizes[i] == BB * DD * NPTS) x      = (const float*)d_in[i];
        else if (in_sizes[i] == OO * 2 * DD)    W      = (const float*)d_in[i];
    }
    float* out = (float*)d_out;

    sort_kernel<<<BB, 1024>>>(points);

    int knn_blocks = BB * (NPTS / KNN_WARPS);          // 4096
    fused_pre_knn_kernel<<<PRE_BLOCKS + knn_blocks, 256>>>(points, x, W);

    edgeconv_kernel<<<dim3(NPTS / 32, BB), 256>>>(out);
}

// round 12
// speedup vs baseline: 1.1381x; 1.1381x over previous
#include <cuda_runtime.h>
#include <cstdint>

#define BB 4
#define FF 3
#define NPTS 8192
#define DD 16
#define KNN_K 32
#define OO 64
#define ALPHA 0.2f

#define GS 64                       // 64x64 grid over (x,y)
#define XG (-4.0f)
#define CW 0.125f                   // 2^-3, exact binary
#define INV_CW 8.0f
#define PRUNE_MARGIN 1e-3f
#define MIN_SEED 48

#define KNN_WARPS 8
#define PRE_BLOCKS 128              // 128*256 = 32768 = B*N

// Scratch (device globals -- no allocations allowed)
__device__ float  g_y1[BB * NPTS * OO];
__device__ float  g_c [BB * NPTS * OO];
__device__ int    g_idx[BB * NPTS * KNN_K];
__device__ float4 g_spts[BB * NPTS];             // cell-sorted (x,y,z, idx-bits)
__device__ int    g_cstart[BB * (GS * GS + 1)];  // cell CSR offsets

// ---------------------------------------------------------------------------
__device__ __forceinline__ int clampi(int v, int lo, int hi)
{ return min(max(v, lo), hi); }

__device__ __forceinline__ int cell_of(float px, float py)
{
    int ix = clampi((int)floorf((px - XG) * INV_CW), 0, GS - 1);
    int iy = clampi((int)floorf((py - XG) * INV_CW), 0, GS - 1);
    return iy * GS + ix;
}

// order-preserving float->u32 map and inverse
__device__ __forceinline__ unsigned mapf(float dpos)
{
    unsigned ub = __float_as_uint(dpos);
    return ub ^ (((unsigned)((int)ub >> 31)) | 0x80000000u);
}
__device__ __forceinline__ float unmapf(unsigned m)
{
    unsigned ub = (m & 0x80000000u) ? (m ^ 0x80000000u) : ~m;
    return __uint_as_float(ub);
}

// ---------------------------------------------------------------------------
// Kernel A: per-batch counting sort of points into 4096 (y,x) cells.
// ---------------------------------------------------------------------------
__global__ __launch_bounds__(1024) void sort_kernel(const float* __restrict__ points)
{
    __shared__ int hist[GS * GS];       // 16 KB
    __shared__ int wsum[32];
    const unsigned FULL = 0xFFFFFFFFu;
    int b = blockIdx.x, tid = threadIdx.x;
    const float* pb = points + b * FF * NPTS;

#pragma unroll
    for (int k = 0; k < 4; k++) hist[tid + k * 1024] = 0;
    __syncthreads();

    for (int m = tid; m < NPTS; m += 1024)
        atomicAdd(&hist[cell_of(pb[m], pb[NPTS + m])], 1);
    __syncthreads();

    // block exclusive scan over 4096 bins (4 bins/thread)
    int base = tid * 4;
    int c0 = hist[base], c1 = hist[base + 1], c2 = hist[base + 2], c3 = hist[base + 3];
    int tsum = c0 + c1 + c2 + c3;
    int lane = tid & 31, wid = tid >> 5;
    int v = tsum;
#pragma unroll
    for (int off = 1; off < 32; off <<= 1) {
        int u = __shfl_up_sync(FULL, v, off);
        if (lane >= off) v += u;
    }
    if (lane == 31) wsum[wid] = v;
    __syncthreads();
    if (tid < 32) {
        int w = wsum[tid];
#pragma unroll
        for (int off = 1; off < 32; off <<= 1) {
            int u = __shfl_up_sync(FULL, w, off);
            if (tid >= off) w += u;
        }
        wsum[tid] = w;                  // inclusive warp totals
    }
    __syncthreads();
    int ex = (v - tsum) + (wid > 0 ? wsum[wid - 1] : 0);
    int b0 = ex, b1 = ex + c0, b2 = b1 + c1, b3 = b2 + c2;
    int* cst = g_cstart + b * (GS * GS + 1);
    cst[base] = b0; cst[base + 1] = b1; cst[base + 2] = b2; cst[base + 3] = b3;
    if (tid == 0) cst[GS * GS] = NPTS;
    __syncthreads();
    hist[base] = b0; hist[base + 1] = b1; hist[base + 2] = b2; hist[base + 3] = b3;
    __syncthreads();

    for (int m = tid; m < NPTS; m += 1024) {
        float px = pb[m], py = pb[NPTS + m], pz = pb[2 * NPTS + m];
        int pos = atomicAdd(&hist[cell_of(px, py)], 1);
        g_spts[b * NPTS + pos] = make_float4(px, py, pz, __int_as_float(m));
    }
}

// ---------------------------------------------------------------------------
// Kernel B (fused): blocks [0,PRE_BLOCKS) = feature projections;
// rest = 2D-grid-pruned 32-NN, warp-per-query, batched-merge top-32.
//
// R11 change vs validated R9: warp gw processes the query at SORTED
// position gw (coords + original index from g_spts[gw]). A block's 64
// queries are spatially adjacent, so their walks touch the same cells ->
// candidate loads become L1-resident after first touch. Pure permutation
// of query->warp assignment; per-query arithmetic/keys/prune/merge are
// the R9 bits verbatim => identical neighbor sets.
// ---------------------------------------------------------------------------
__global__ __launch_bounds__(256) void fused_pre_knn_kernel(
    const float* __restrict__ points,
    const float* __restrict__ x,
    const float* __restrict__ W)
{
    __shared__ float sW[OO * 2 * DD];                    // precompute branch
    __shared__ int   scs[GS * GS + 1];                   // knn branch: cell CSR
    __shared__ unsigned long long sbuf[KNN_WARPS * 32];  // per-warp key buffer

    int tid = threadIdx.x;

    if (blockIdx.x < PRE_BLOCKS) {
        for (int i = tid; i < OO * 2 * DD; i += 256) sW[i] = W[i];
        __syncthreads();

        int gid = blockIdx.x * 256 + tid;
        int b = gid / NPTS, n = gid % NPTS;

        float xv[DD];
#pragma unroll
        for (int d = 0; d < DD; d++) xv[d] = x[(b * DD + d) * NPTS + n];

        float* y1p = &g_y1[(b * NPTS + n) * OO];
        float* cp  = &g_c [(b * NPTS + n) * OO];
#pragma unroll 4
        for (int o = 0; o < OO; o++) {
            float s1 = 0.f, s2 = 0.f;
#pragma unroll
            for (int d = 0; d < DD; d++) {
                s1 = __fmaf_rn(sW[o * 2 * DD + d],      xv[d], s1);
                s2 = __fmaf_rn(sW[o * 2 * DD + DD + d], xv[d], s2);
            }
            y1p[o] = s1;
            cp[o]  = s2 - s1;
        }
        return;
    }

    // ---------------------- knn: warp-per-query (sorted order) -----------
    int bid  = blockIdx.x - PRE_BLOCKS;
    int b    = bid >> 10;                        // 1024 blocks per batch
    int nblk = bid & 1023;
    int wid  = tid >> 5;
    int lane = tid & 31;
    int gw = nblk * KNN_WARPS + wid;             // sorted query position

    for (int j = tid; j < GS * GS + 1; j += 256)
        scs[j] = g_cstart[b * (GS * GS + 1) + j];
    __syncthreads();

    const float4* sp = g_spts + b * NPTS;
    const unsigned FULL = 0xFFFFFFFFu;
    unsigned long long* wbuf = &sbuf[wid * 32];

    float4 q4 = sp[gw];                          // this warp's query
    float qx = q4.x, qy = q4.y, qz = q4.z;
    int norig = __float_as_int(q4.w);            // original point index
    float xxn = __fadd_rn(__fadd_rn(__fmul_rn(qx, qx), __fmul_rn(qy, qy)),
                          __fmul_rn(qz, qz));
    float nxxn = -xxn;
    int qix = clampi((int)floorf((qx - XG) * INV_CW), 0, GS - 1);
    int qiy = clampi((int)floorf((qy - XG) * INV_CW), 0, GS - 1);

    unsigned long long listk = 0xFFFFFFFF00000000ULL | (unsigned)lane;
    unsigned long long worst = 0xFFFFFFFF0000001FULL;
    int nbuf = 0;                                // warp-uniform

    // flush: bitonic-sort buffer, half-clean vs list, bitonic re-merge
    auto flush = [&]() {
        __syncwarp(FULL);
        unsigned long long v = (lane < nbuf) ? wbuf[lane]
                                             : 0xFFFFFFFFFFFFFFFFULL;
#pragma unroll
        for (int k = 2; k <= 32; k <<= 1) {
#pragma unroll
            for (int j = k >> 1; j > 0; j >>= 1) {
                unsigned long long v2 = __shfl_xor_sync(FULL, v, j);
                bool asc   = ((lane & k) == 0);
                bool lower = ((lane & j) == 0);
                unsigned long long mn = (v < v2) ? v : v2;
                unsigned long long mx = (v < v2) ? v2 : v;
                v = (asc == lower) ? mn : mx;
            }
        }
        unsigned long long vr = __shfl_sync(FULL, v, 31 - lane);
        unsigned long long w = (listk < vr) ? listk : vr;
#pragma unroll
        for (int j = 16; j > 0; j >>= 1) {
            unsigned long long w2 = __shfl_xor_sync(FULL, w, j);
            bool lower = ((lane & j) == 0);
            unsigned long long mn = (w < w2) ? w : w2;
            unsigned long long mx = (w < w2) ? w2 : w;
            w = lower ? mn : mx;
        }
        listk = w;
        worst = __shfl_sync(FULL, listk, 31);
        nbuf = 0;
    };

    auto stream = [&](int beg, int end) {
        if (beg >= end) return;
        float4 c = (beg + lane < end) ? __ldg(&sp[beg + lane])
                                      : make_float4(0.f, 0.f, 0.f, 0.f);
        for (int g = beg; g < end; g += 32) {
            int i2 = g + 32 + lane;
            float4 cn = (i2 < end) ? __ldg(&sp[i2])
                                   : make_float4(0.f, 0.f, 0.f, 0.f);
            bool valid = (g + lane) < end;
            float xxm = __fadd_rn(
                __fadd_rn(__fmul_rn(c.x, c.x), __fmul_rn(c.y, c.y)),
                __fmul_rn(c.z, c.z));
            float ss = __fmul_rn(qx, c.x);
            ss = __fmaf_rn(qy, c.y, ss);
            ss = __fmaf_rn(qz, c.z, ss);
            float d = __fsub_rn(xxm, __fmaf_rn(ss, 2.0f, nxxn));
            unsigned long long key = valid
                ? (((unsigned long long)mapf(d) << 32) |
                   (unsigned)__float_as_int(c.w))
                : 0xFFFFFFFFFFFFFFFFULL;

            unsigned pass = __ballot_sync(FULL, key < worst);
            if (pass) {
                int npass = __popc(pass);
                if (nbuf + npass > 32) flush();          // warp-uniform
                int rank = __popc(pass & ((1u << lane) - 1u));
                if (pass & (1u << lane)) wbuf[nbuf + rank] = key;
                nbuf += npass;
            }
            c = cn;
        }
    };

    // conservative x-interval for a row; (1,0) only when row excluded
    auto rowrange = [&](int iy) -> int2 {
        float wd = unmapf((unsigned)(worst >> 32));
        if (wd != wd) return make_int2(0, GS - 1);     // sentinel: full row
        float dy = 0.f;
        if (iy > qiy)      dy = fmaxf(__fsub_rn(XG + (float)iy * CW, qy), 0.f);
        else if (iy < qiy) dy = fmaxf(__fsub_rn(qy, XG + (float)(iy + 1) * CW), 0.f);
        float rem = wd + PRUNE_MARGIN - __fmul_rn(dy, dy);
        if (rem < 0.f) return make_int2(1, 0);          // row excluded
        float rad = sqrtf(rem);
        int jlo = (int)floorf((qx - rad - XG) * INV_CW) - 1;
        int jhi = (int)floorf((qx + rad - XG) * INV_CW) + 1;
        jlo = clampi(jlo, 0, GS - 1);
        jhi = clampi(jhi, 0, GS - 1);
        return make_int2(jlo, jhi);
    };

    // seed: own row, interval around own cell with >= MIN_SEED points
    int slo = qix, shi = qix;
    {
        const int* rc = &scs[qiy * GS];
        int cnt = rc[shi + 1] - rc[slo];
        while (cnt < MIN_SEED && (slo > 0 || shi < GS - 1)) {
            if (slo > 0) slo--;
            if (shi < GS - 1) shi++;
            cnt = rc[shi + 1] - rc[slo];
        }
        stream(rc[slo], rc[shi + 1]);
        if (nbuf > 0) flush();          // real worst for pruning
    }
    // own row remainder (outside seed interval)
    {
        int2 rr = rowrange(qiy);
        if (rr.x <= rr.y) {
            const int* rc = &scs[qiy * GS];
            if (rr.x < slo) stream(rc[rr.x], rc[slo]);
            if (rr.y > shi) stream(rc[shi + 1], rc[rr.y + 1]);
        }
    }
    // alternate rows outward; a direction stops when its row is excluded
    int up = qiy + 1, dn = qiy - 1;
    bool goU = (up < GS), goD = (dn >= 0);
    while (goU || goD) {
        if (goU) {
            int2 rr = rowrange(up);
            if (rr.x > rr.y) goU = false;
            else {
                const int* rc = &scs[up * GS];
                stream(rc[rr.x], rc[rr.y + 1]);
                up++; if (up >= GS) goU = false;
            }
        }
        if (goD) {
            int2 rr = rowrange(dn);
            if (rr.x > rr.y) goD = false;
            else {
                const int* rc = &scs[dn * GS];
                stream(rc[rr.x], rc[rr.y + 1]);
                dn--; if (dn < 0) goD = false;
            }
        }
    }
    if (nbuf > 0) flush();

    g_idx[(b * NPTS + norig) * KNN_K + lane] = (int)(listk & 0xFFFFFFFFu);
}

// ---------------------------------------------------------------------------
// Kernel 3: out[b][o][n] = (1/K) * sum_k leaky( y1[b][idx[n][k]][o] + c[b][n][o] )
// ---------------------------------------------------------------------------
__global__ __launch_bounds__(256) void edgeconv_kernel(float* __restrict__ out)
{
    __shared__ float stile[OO][33];
    __shared__ int   sidx[32 * KNN_K];

    int b = blockIdx.y;
    int nbase = blockIdx.x * 32;
    int tid = threadIdx.x;

    for (int i = tid; i < 32 * KNN_K; i += 256)
        sidx[i] = g_idx[(b * NPTS + nbase) * KNN_K + i];
    __syncthreads();

    int o = tid & 63;
    int sub = tid >> 6;

    for (int nt = 0; nt < 8; nt++) {
        int nl = nt * 4 + sub;
        int n = nbase + nl;
        float c = g_c[(b * NPTS + n) * OO + o];
        float acc = 0.f;
        const int* ip = &sidx[nl * KNN_K];
#pragma unroll 8
        for (int k = 0; k < KNN_K; k++) {
            int m = ip[k];
            float t = g_y1[(b * NPTS + m) * OO + o] + c;
            acc += (t >= 0.f) ? t : ALPHA * t;
        }
        stile[o][nl] = acc * (1.0f / KNN_K);
    }
    __syncthreads();

#pragma unroll
    for (int r = 0; r < 8; r++) {
        int oo = r * 8 + (tid >> 5);
        int nn = tid & 31;
        out[(b * OO + oo) * NPTS + nbase + nn] = stile[oo][nn];
    }
}

// ---------------------------------------------------------------------------
extern "C" void kernel_launch(void* const* d_in, const int* in_sizes, int n_in,
                              void* d_out, int out_size)
{
    const float* points = nullptr;
    const float* x = nullptr;
    const float* W = nullptr;
    for (int i = 0; i < n_in; i++) {
        if      (in_sizes[i] == BB * FF * NPTS) points = (const float*)d_in[i];
        else if (in_sizes[i] == BB * DD * NPTS) x      = (const float*)d_in[i];
        else if (in_sizes[i] == OO * 2 * DD)    W      = (const float*)d_in[i];
    }
    float* out = (float*)d_out;

    sort_kernel<<<BB, 1024>>>(points);

    int knn_blocks = BB * (NPTS / KNN_WARPS);          // 4096
    fused_pre_knn_kernel<<<PRE_BLOCKS + knn_blocks, 256>>>(points, x, W);

    edgeconv_kernel<<<dim3(NPTS / 32, BB), 256>>>(out);
}